// round 13
// baseline (speedup 1.0000x reference)
#include <cuda_runtime.h>
#include <cstdint>

#define BATCH 32
#define NN    784
#define DD    512
#define RESO  28
#define KK    10
#define BT    112
#define NTB   7
#define NPAIR 28          // triangular tile pairs (p<=q)
#define NTHR  224         // 16 x 14 threads
#define KC    16          // k-chunk depth
#define SA_ST 121         // u64 per k-row of A (112 + 9 pad; odd*2 words => spread banks)
#define SB_ST 58          // u64 per k-row of B (56+2 pad)
#define SD_ST 113         // dist-tile stride (floats, odd => conflict-free both ways)
#define INF_VAL 100000.0f

typedef unsigned long long ull;

__device__ __align__(256) float g_xn[(size_t)BATCH * NN * DD];
__device__ __align__(256) float g_sq[BATCH * NN];
__device__ __align__(256) ull   g_part[(size_t)BATCH * NN * NTB * KK];   // 14 MB

__device__ __forceinline__ ull fma2(ull a, ull b, ull c) {
    ull d; asm("fma.rn.f32x2 %0,%1,%2,%3;" : "=l"(d) : "l"(a), "l"(b), "l"(c)); return d;
}
__device__ __forceinline__ ull dup2(float x) {
    ull d; asm("mov.b64 %0,{%1,%1};" : "=l"(d) : "f"(x)); return d;
}
__device__ __forceinline__ float lo2(ull v) { return __uint_as_float((unsigned)v); }
__device__ __forceinline__ float hi2(ull v) { return __uint_as_float((unsigned)(v >> 32)); }
__device__ __forceinline__ unsigned fmap(float v) {
    unsigned u = __float_as_uint(v);
    return (u & 0x80000000u) ? ~u : (u | 0x80000000u);   // order-preserving map
}

// ---------- Kernel 1: exact-rounding normalize (warp per vector) ----------
__global__ void norm_kernel(const float* __restrict__ in) {
    const int vec  = blockIdx.x * 8 + (threadIdx.x >> 5);
    const int lane = threadIdx.x & 31;
    const float4* v = reinterpret_cast<const float4*>(in + (size_t)vec * DD);
    float4 a0 = v[lane], a1 = v[lane + 32], a2 = v[lane + 64], a3 = v[lane + 96];

    float s = 0.0f;
    s = fmaf(a0.x,a0.x,s); s = fmaf(a0.y,a0.y,s); s = fmaf(a0.z,a0.z,s); s = fmaf(a0.w,a0.w,s);
    s = fmaf(a1.x,a1.x,s); s = fmaf(a1.y,a1.y,s); s = fmaf(a1.z,a1.z,s); s = fmaf(a1.w,a1.w,s);
    s = fmaf(a2.x,a2.x,s); s = fmaf(a2.y,a2.y,s); s = fmaf(a2.z,a2.z,s); s = fmaf(a2.w,a2.w,s);
    s = fmaf(a3.x,a3.x,s); s = fmaf(a3.y,a3.y,s); s = fmaf(a3.z,a3.z,s); s = fmaf(a3.w,a3.w,s);
    #pragma unroll
    for (int off = 16; off > 0; off >>= 1)
        s = __fadd_rn(s, __shfl_xor_sync(0xffffffffu, s, off));

    const float nrm = fmaxf(__fsqrt_rn(s), 1e-12f);
    a0.x=__fdiv_rn(a0.x,nrm); a0.y=__fdiv_rn(a0.y,nrm); a0.z=__fdiv_rn(a0.z,nrm); a0.w=__fdiv_rn(a0.w,nrm);
    a1.x=__fdiv_rn(a1.x,nrm); a1.y=__fdiv_rn(a1.y,nrm); a1.z=__fdiv_rn(a1.z,nrm); a1.w=__fdiv_rn(a1.w,nrm);
    a2.x=__fdiv_rn(a2.x,nrm); a2.y=__fdiv_rn(a2.y,nrm); a2.z=__fdiv_rn(a2.z,nrm); a2.w=__fdiv_rn(a2.w,nrm);
    a3.x=__fdiv_rn(a3.x,nrm); a3.y=__fdiv_rn(a3.y,nrm); a3.z=__fdiv_rn(a3.z,nrm); a3.w=__fdiv_rn(a3.w,nrm);

    float s2 = 0.0f;
    s2 = fmaf(a0.x,a0.x,s2); s2 = fmaf(a0.y,a0.y,s2); s2 = fmaf(a0.z,a0.z,s2); s2 = fmaf(a0.w,a0.w,s2);
    s2 = fmaf(a1.x,a1.x,s2); s2 = fmaf(a1.y,a1.y,s2); s2 = fmaf(a1.z,a1.z,s2); s2 = fmaf(a1.w,a1.w,s2);
    s2 = fmaf(a2.x,a2.x,s2); s2 = fmaf(a2.y,a2.y,s2); s2 = fmaf(a2.z,a2.z,s2); s2 = fmaf(a2.w,a2.w,s2);
    s2 = fmaf(a3.x,a3.x,s2); s2 = fmaf(a3.y,a3.y,s2); s2 = fmaf(a3.z,a3.z,s2); s2 = fmaf(a3.w,a3.w,s2);
    #pragma unroll
    for (int off = 16; off > 0; off >>= 1)
        s2 = __fadd_rn(s2, __shfl_xor_sync(0xffffffffu, s2, off));

    float4* o = reinterpret_cast<float4*>(g_xn + (size_t)vec * DD);
    o[lane] = a0; o[lane + 32] = a1; o[lane + 64] = a2; o[lane + 96] = a3;
    if (lane == 0) g_sq[vec] = s2;
}

// ---------- Kernel 2: symmetric GEMM + dist + in-block partial top-K ----------
// A staged PRE-DUPLICATED as u64 {x,x}: inner loop uses one LDS.64 per A value
// (no per-FMA dup movs). B staged as packed column-pair f32x2.
__global__ void __launch_bounds__(NTHR, 2)
MediumRangeEdge_11072425689094_kernel(const float* __restrict__ rel) {
    extern __shared__ char smraw[];
    ull*   sA0 = (ull*)smraw;                      // [16][SA_ST] 15488 B
    ull*   sA1 = (ull*)(smraw + 15488);
    ull*   sB0 = (ull*)(smraw + 30976);            // [16][SB_ST] 7424 B
    ull*   sB1 = (ull*)(smraw + 38400);            // end 45824
    float* sD  = (float*)smraw;                    // [112][SD_ST] 50624 B (aliases staging)

    const int b = blockIdx.x / NPAIR;
    int rem = blockIdx.x - b * NPAIR;
    int p = 0, cnt = NTB;
    while (rem >= cnt) { rem -= cnt; --cnt; ++p; }
    const int q = p + rem;
    const int pbase = p * BT, qbase = q * BT;

    const int tid = threadIdx.x;
    const int tx  = tid & 15;
    const int ty  = tid >> 4;

    const int r0 = tid >> 2,          kq0 = tid & 3;
    const int r1 = (tid + NTHR) >> 2, kq1 = (tid + NTHR) & 3;

    const float4* gA = (const float4*)(g_xn + ((size_t)b * NN + pbase) * DD);
    const float4* gB = (const float4*)(g_xn + ((size_t)b * NN + qbase) * DD);

    float4 fa0 = gA[r0 * (DD/4) + kq0], fa1 = gA[r1 * (DD/4) + kq1];
    float4 fb0 = gB[r0 * (DD/4) + kq0], fb1 = gB[r1 * (DD/4) + kq1];

    ull acc[7][4];
    #pragma unroll
    for (int s = 0; s < 7; ++s)
        #pragma unroll
        for (int c = 0; c < 4; ++c) acc[s][c] = 0ULL;

    for (int kc = 0; kc < DD / KC; ++kc) {
        ull* A  = (kc & 1) ? sA1 : sA0;
        ull* Bq = (kc & 1) ? sB1 : sB0;
        float* Bf = (float*)Bq;

        // STS A: k-major scatter of DUPLICATED pairs (STS.64)
        A[(4*kq0+0)*SA_ST + r0] = dup2(fa0.x);
        A[(4*kq0+1)*SA_ST + r0] = dup2(fa0.y);
        A[(4*kq0+2)*SA_ST + r0] = dup2(fa0.z);
        A[(4*kq0+3)*SA_ST + r0] = dup2(fa0.w);
        A[(4*kq1+0)*SA_ST + r1] = dup2(fa1.x);
        A[(4*kq1+1)*SA_ST + r1] = dup2(fa1.y);
        A[(4*kq1+2)*SA_ST + r1] = dup2(fa1.z);
        A[(4*kq1+3)*SA_ST + r1] = dup2(fa1.w);
        // STS B: column-pair packed f32x2
        {
            const int c2 = r0 >> 1, h = r0 & 1;
            Bf[((4*kq0+0)*SB_ST + c2)*2 + h] = fb0.x;
            Bf[((4*kq0+1)*SB_ST + c2)*2 + h] = fb0.y;
            Bf[((4*kq0+2)*SB_ST + c2)*2 + h] = fb0.z;
            Bf[((4*kq0+3)*SB_ST + c2)*2 + h] = fb0.w;
        }
        {
            const int c2 = r1 >> 1, h = r1 & 1;
            Bf[((4*kq1+0)*SB_ST + c2)*2 + h] = fb1.x;
            Bf[((4*kq1+1)*SB_ST + c2)*2 + h] = fb1.y;
            Bf[((4*kq1+2)*SB_ST + c2)*2 + h] = fb1.z;
            Bf[((4*kq1+3)*SB_ST + c2)*2 + h] = fb1.w;
        }
        __syncthreads();

        if (kc + 1 < DD / KC) {
            const int ko = (kc + 1) * (KC / 4);
            fa0 = gA[r0*(DD/4) + ko + kq0]; fa1 = gA[r1*(DD/4) + ko + kq1];
            fb0 = gB[r0*(DD/4) + ko + kq0]; fb1 = gB[r1*(DD/4) + ko + kq1];
        }

        const ull* Ar = A + tx;
        const ull* Br = Bq + 4 * ty;
        #pragma unroll
        for (int kk = 0; kk < KC; ++kk) {
            const ulonglong2 bb0 = *(const ulonglong2*)(Br + kk*SB_ST);
            const ulonglong2 bb1 = *(const ulonglong2*)(Br + kk*SB_ST + 2);
            #pragma unroll
            for (int s = 0; s < 7; ++s) {
                const ull av = Ar[kk*SA_ST + 16*s];    // pre-duplicated {x,x}
                acc[s][0] = fma2(av, bb0.x, acc[s][0]);
                acc[s][1] = fma2(av, bb0.y, acc[s][1]);
                acc[s][2] = fma2(av, bb1.x, acc[s][2]);
                acc[s][3] = fma2(av, bb1.y, acc[s][3]);
            }
        }
        __syncthreads();
    }

    // ---- epilogue: dist tile into sD ----
    float sqj[8]; int jr[8], jc[8];
    #pragma unroll
    for (int cc = 0; cc < 8; ++cc) {
        const int j = qbase + 8*ty + cc;
        sqj[cc] = g_sq[b*NN + j];
        jr[cc] = j / RESO; jc[cc] = j - jr[cc]*RESO;
    }
    #pragma unroll
    for (int s = 0; s < 7; ++s) {
        const int i  = pbase + tx + 16*s;
        const float sqi = g_sq[b*NN + i];
        const int ri = i / RESO, ci = i - ri*RESO;
        const float4 rl0 = *(const float4*)(rel + (size_t)i*NN + qbase + 8*ty);
        const float4 rl1 = *(const float4*)(rel + (size_t)i*NN + qbase + 8*ty + 4);
        const float rv[8] = {rl0.x, rl0.y, rl0.z, rl0.w, rl1.x, rl1.y, rl1.z, rl1.w};
        float* drow = sD + (tx + 16*s) * SD_ST + 8*ty;
        #pragma unroll
        for (int c = 0; c < 4; ++c) {
            const float d0 = lo2(acc[s][c]), d1 = hi2(acc[s][c]);
            float v0 = __fadd_rn(__fsub_rn(__fadd_rn(sqi, sqj[2*c]),
                                           __fmul_rn(2.0f, d0)), rv[2*c]);
            float v1 = __fadd_rn(__fsub_rn(__fadd_rn(sqi, sqj[2*c+1]),
                                           __fmul_rn(2.0f, d1)), rv[2*c+1]);
            int dr = ri - jr[2*c],   dc = ci - jc[2*c];
            if (dr >= -1 && dr <= 1 && dc >= -1 && dc <= 1) v0 = __fadd_rn(v0, INF_VAL);
            dr = ri - jr[2*c+1]; dc = ci - jc[2*c+1];
            if (dr >= -1 && dr <= 1 && dc >= -1 && dc <= 1) v1 = __fadd_rn(v1, INF_VAL);
            drow[2*c] = v0; drow[2*c+1] = v1;
        }
    }
    __syncthreads();

    // ---- in-block partial top-K: one thread per (row, side) ----
    ull list[KK];
    #pragma unroll
    for (int qq = 0; qq < KK; ++qq) list[qq] = ~0ULL;

    if (tid < BT) {
        const float* rowp = sD + tid * SD_ST;
        #pragma unroll 4
        for (int c = 0; c < BT; ++c) {
            const ull key = ((ull)fmap(rowp[c]) << 32) | (unsigned)(qbase + c);
            if (key < list[KK-1]) {
                list[KK-1] = key;
                #pragma unroll
                for (int qq = KK-1; qq > 0; --qq)
                    if (list[qq] < list[qq-1]) {
                        const ull tk = list[qq-1]; list[qq-1] = list[qq]; list[qq] = tk;
                    }
            }
        }
        ull* dst = g_part + ((size_t)(b*NN + pbase + tid) * NTB + q) * KK;
        #pragma unroll
        for (int m = 0; m < KK/2; ++m)
            *(ulonglong2*)(dst + 2*m) = make_ulonglong2(list[2*m], list[2*m+1]);
    } else if (p != q) {
        const int l = tid - BT;
        #pragma unroll 4
        for (int r = 0; r < BT; ++r) {
            const ull key = ((ull)fmap(sD[r * SD_ST + l]) << 32) | (unsigned)(pbase + r);
            if (key < list[KK-1]) {
                list[KK-1] = key;
                #pragma unroll
                for (int qq = KK-1; qq > 0; --qq)
                    if (list[qq] < list[qq-1]) {
                        const ull tk = list[qq-1]; list[qq-1] = list[qq]; list[qq] = tk;
                    }
            }
        }
        ull* dst = g_part + ((size_t)(b*NN + qbase + l) * NTB + p) * KK;
        #pragma unroll
        for (int m = 0; m < KK/2; ++m)
            *(ulonglong2*)(dst + 2*m) = make_ulonglong2(list[2*m], list[2*m+1]);
    }
}

// ---------- Kernel 3: merge 7 partial lists per row -> edges ----------
__global__ void __launch_bounds__(256)
merge_kernel(float* __restrict__ out) {
    const int row  = blockIdx.x * 8 + (threadIdx.x >> 5);   // global row (b*N+i)
    const int lane = threadIdx.x & 31;
    const ull* part = g_part + (size_t)row * (NTB * KK);    // 70 keys

    ull a = part[lane];
    ull c2 = part[lane + 32];
    ull c3 = (lane < NTB*KK - 64) ? part[lane + 64] : ~0ULL;
    if (c2 < a)  { const ull t = a;  a  = c2; c2 = t; }
    if (c3 < c2) { const ull t = c2; c2 = c3; c3 = t; }
    if (c2 < a)  { const ull t = a;  a  = c2; c2 = t; }

    const int bofs = (row / NN) * NN;
    const int base = row * (KK * 3);
    #pragma unroll
    for (int k = 0; k < KK; ++k) {
        ull v = a;
        #pragma unroll
        for (int off = 16; off > 0; off >>= 1) {
            const ull o = __shfl_xor_sync(0xffffffffu, v, off);
            if (o < v) v = o;
        }
        if (lane == k) {
            out[base + 3*k + 0] = (float)((int)(v & 0xffffffffULL) + bofs);  // dst
            out[base + 3*k + 1] = (float)row;                                // src
            out[base + 3*k + 2] = 0.0f;                                      // relation
        }
        if (a == v) { a = c2; c2 = c3; c3 = ~0ULL; }
    }
}

extern "C" void kernel_launch(void* const* d_in, const int* in_sizes, int n_in,
                              void* d_out, int out_size) {
    (void)out_size;
    const float* node_feature = (const float*)d_in[0];
    const float* relative_pos = (const float*)d_in[1];
    if (n_in >= 2 && in_sizes[0] < in_sizes[1]) {
        node_feature = (const float*)d_in[1];
        relative_pos = (const float*)d_in[0];
    }
    float* out = (float*)d_out;

    const int smem = BT * SD_ST * (int)sizeof(float);   // 50624 B (covers staging)
    static int attr_done = 0;
    if (!attr_done) {
        cudaFuncSetAttribute(MediumRangeEdge_11072425689094_kernel,
                             cudaFuncAttributeMaxDynamicSharedMemorySize, smem);
        attr_done = 1;
    }

    norm_kernel<<<(BATCH * NN) / 8, 256>>>(node_feature);
    MediumRangeEdge_11072425689094_kernel<<<BATCH * NPAIR, NTHR, smem>>>(relative_pos);
    merge_kernel<<<(BATCH * NN) / 8, 256>>>(out);
}

// round 15
// speedup vs baseline: 1.3119x; 1.3119x over previous
#include <cuda_runtime.h>
#include <cstdint>

#define BATCH 32
#define NNV   784
#define NPAD  896
#define DD    512
#define RESO  28
#define KK    10
#define MT    128
#define NTB   7
#define NPAIR 28
#define NTHR  256
#define INF_VAL 100000.0f
#define SD_ST 129
#define BUF_SZ 65536            // 4 sub-tiles x 16KB
#define SMEM_TOTAL (2 * BUF_SZ)

typedef unsigned long long ull;

__device__ __align__(256) unsigned short g_hi[(size_t)BATCH * NPAD * DD];  // zero-padded
__device__ __align__(256) unsigned short g_lo[(size_t)BATCH * NPAD * DD];
__device__ __align__(256) float g_sq[BATCH * NPAD];
__device__ __align__(256) ull   g_part[(size_t)BATCH * NNV * NTB * KK];

// ---------------- helpers ----------------
__device__ __forceinline__ unsigned smem_u32(const void* p) {
    unsigned a;
    asm("{ .reg .u64 t; cvta.to.shared.u64 t, %1; cvt.u32.u64 %0, t; }" : "=r"(a) : "l"(p));
    return a;
}
__device__ __forceinline__ unsigned pack2bf(float lo, float hi) {
    unsigned r;   // first PTX src -> upper half
    asm("cvt.rn.bf16x2.f32 %0, %2, %1;" : "=r"(r) : "f"(lo), "f"(hi));
    return r;
}
__device__ __forceinline__ unsigned fmap(float v) {
    unsigned u = __float_as_uint(v);
    return (u & 0x80000000u) ? ~u : (u | 0x80000000u);
}
__device__ __forceinline__ void kinsert(ull* list, ull key) {
    if (key < list[KK - 1]) {
        list[KK - 1] = key;
        #pragma unroll
        for (int z = KK - 1; z > 0; --z)
            if (list[z] < list[z - 1]) { ull t = list[z-1]; list[z-1] = list[z]; list[z] = t; }
    }
}
__device__ __forceinline__ void write_part(int row, int tile, const ull* list) {
    ull* dst = g_part + ((size_t)row * NTB + tile) * KK;
    #pragma unroll
    for (int m = 0; m < KK; m += 2)
        *(ulonglong2*)(dst + m) = make_ulonglong2(list[m], list[m + 1]);
}
__device__ __forceinline__ void ldm_x4(unsigned* f, unsigned addr) {
    asm volatile("ldmatrix.sync.aligned.m8n8.x4.shared.b16 {%0,%1,%2,%3}, [%4];"
                 : "=r"(f[0]), "=r"(f[1]), "=r"(f[2]), "=r"(f[3]) : "r"(addr));
}
__device__ __forceinline__ void mma16816(float* c, const unsigned* a, const unsigned* b) {
    asm volatile("mma.sync.aligned.m16n8k16.row.col.f32.bf16.bf16.f32 "
                 "{%0,%1,%2,%3}, {%4,%5,%6,%7}, {%8,%9}, {%0,%1,%2,%3};"
                 : "+f"(c[0]), "+f"(c[1]), "+f"(c[2]), "+f"(c[3])
                 : "r"(a[0]), "r"(a[1]), "r"(a[2]), "r"(a[3]), "r"(b[0]), "r"(b[1]));
}

// ---------------- Kernel 1: normalize + bf16 hi/lo split ----------------
__global__ void norm_kernel(const float* __restrict__ in) {
    const int vec  = blockIdx.x * 8 + (threadIdx.x >> 5);
    const int lane = threadIdx.x & 31;
    const float4* v = reinterpret_cast<const float4*>(in + (size_t)vec * DD);
    float4 a0 = v[lane], a1 = v[lane + 32], a2 = v[lane + 64], a3 = v[lane + 96];

    float s = 0.0f;
    s = fmaf(a0.x,a0.x,s); s = fmaf(a0.y,a0.y,s); s = fmaf(a0.z,a0.z,s); s = fmaf(a0.w,a0.w,s);
    s = fmaf(a1.x,a1.x,s); s = fmaf(a1.y,a1.y,s); s = fmaf(a1.z,a1.z,s); s = fmaf(a1.w,a1.w,s);
    s = fmaf(a2.x,a2.x,s); s = fmaf(a2.y,a2.y,s); s = fmaf(a2.z,a2.z,s); s = fmaf(a2.w,a2.w,s);
    s = fmaf(a3.x,a3.x,s); s = fmaf(a3.y,a3.y,s); s = fmaf(a3.z,a3.z,s); s = fmaf(a3.w,a3.w,s);
    #pragma unroll
    for (int off = 16; off > 0; off >>= 1)
        s = __fadd_rn(s, __shfl_xor_sync(0xffffffffu, s, off));

    const float nrm = fmaxf(__fsqrt_rn(s), 1e-12f);
    a0.x=__fdiv_rn(a0.x,nrm); a0.y=__fdiv_rn(a0.y,nrm); a0.z=__fdiv_rn(a0.z,nrm); a0.w=__fdiv_rn(a0.w,nrm);
    a1.x=__fdiv_rn(a1.x,nrm); a1.y=__fdiv_rn(a1.y,nrm); a1.z=__fdiv_rn(a1.z,nrm); a1.w=__fdiv_rn(a1.w,nrm);
    a2.x=__fdiv_rn(a2.x,nrm); a2.y=__fdiv_rn(a2.y,nrm); a2.z=__fdiv_rn(a2.z,nrm); a2.w=__fdiv_rn(a2.w,nrm);
    a3.x=__fdiv_rn(a3.x,nrm); a3.y=__fdiv_rn(a3.y,nrm); a3.z=__fdiv_rn(a3.z,nrm); a3.w=__fdiv_rn(a3.w,nrm);

    float s2 = 0.0f;
    s2 = fmaf(a0.x,a0.x,s2); s2 = fmaf(a0.y,a0.y,s2); s2 = fmaf(a0.z,a0.z,s2); s2 = fmaf(a0.w,a0.w,s2);
    s2 = fmaf(a1.x,a1.x,s2); s2 = fmaf(a1.y,a1.y,s2); s2 = fmaf(a1.z,a1.z,s2); s2 = fmaf(a1.w,a1.w,s2);
    s2 = fmaf(a2.x,a2.x,s2); s2 = fmaf(a2.y,a2.y,s2); s2 = fmaf(a2.z,a2.z,s2); s2 = fmaf(a2.w,a2.w,s2);
    s2 = fmaf(a3.x,a3.x,s2); s2 = fmaf(a3.y,a3.y,s2); s2 = fmaf(a3.z,a3.z,s2); s2 = fmaf(a3.w,a3.w,s2);
    #pragma unroll
    for (int off = 16; off > 0; off >>= 1)
        s2 = __fadd_rn(s2, __shfl_xor_sync(0xffffffffu, s2, off));

    const int bb = vec / NNV;
    const int ii = vec - bb * NNV;
    ull* H = (ull*)g_hi + (size_t)(bb * NPAD + ii) * (DD / 4);
    ull* L = (ull*)g_lo + (size_t)(bb * NPAD + ii) * (DD / 4);

    const float4 av[4] = {a0, a1, a2, a3};
    #pragma unroll
    for (int t = 0; t < 4; ++t) {
        const float4 a = av[t];
        const unsigned h0 = pack2bf(a.x, a.y);
        const unsigned h1 = pack2bf(a.z, a.w);
        const float lx = a.x - __uint_as_float(h0 << 16);
        const float ly = a.y - __uint_as_float(h0 & 0xFFFF0000u);
        const float lz = a.z - __uint_as_float(h1 << 16);
        const float lw = a.w - __uint_as_float(h1 & 0xFFFF0000u);
        const unsigned l0 = pack2bf(lx, ly);
        const unsigned l1 = pack2bf(lz, lw);
        H[lane + 32 * t] = (ull)h0 | ((ull)h1 << 32);
        L[lane + 32 * t] = (ull)l0 | ((ull)l1 << 32);
    }
    if (lane == 0) g_sq[bb * NPAD + ii] = s2;
}

// ---------------- staging: 4 sub-tiles (p-hi, p-lo, q-hi, q-lo), swizzled ----------------
__device__ __forceinline__ void stage_chunk(char* buf, int tid, int b,
                                            int pbase, int qbase, int chunk) {
    #pragma unroll
    for (int st = 0; st < 4; ++st) {
        const unsigned short* src = (st & 1) ? g_lo : g_hi;
        const int rowb = b * NPAD + ((st < 2) ? pbase : qbase);
        char* dst = buf + st * 16384;
        #pragma unroll
        for (int u = 0; u < 4; ++u) {
            const int idx = tid + 256 * u;
            const int r = idx >> 3, g = idx & 7;
            const uint4 v = *(const uint4*)(src + (size_t)(rowb + r) * DD + chunk * 64 + g * 8);
            *(uint4*)(dst + r * 128 + ((g ^ (r & 7)) << 4)) = v;
        }
    }
}

// ---------------- Kernel 2: bf16 mma.sync GEMM + dist + partial top-K ----------------
__global__ void __launch_bounds__(NTHR, 1)
MediumRangeEdge_11072425689094_kernel(const float* __restrict__ rel) {
    extern __shared__ char sm[];
    const unsigned smb = smem_u32(sm);

    const int b = blockIdx.x / NPAIR;
    int rem = blockIdx.x - b * NPAIR;
    int p = 0, cnt = NTB;
    while (rem >= cnt) { rem -= cnt; --cnt; ++p; }
    const int q = p + rem;
    const int pbase = p * MT, qbase = q * MT;

    const int tid = threadIdx.x;
    const int w   = tid >> 5;
    const int l   = tid & 31;
    const int Rw  = 32 * (w & 3);          // warp rows
    const int Cw  = 64 * (w >> 2);         // warp cols

    float acc[2][8][4] = {};

    // per-thread ldmatrix geometry
    int rA[2];  rA[0] = Rw + (l & 15);  rA[1] = rA[0] + 16;
    const int gA0 = (l >> 4) & 1;
    int nB[4];
    #pragma unroll
    for (int t = 0; t < 4; ++t) nB[t] = Cw + 16 * t + (l & 7) + 8 * ((l >> 4) & 1);
    const int gB0 = (l >> 3) & 1;

    stage_chunk(sm, tid, b, pbase, qbase, 0);
    __syncthreads();

    for (int c = 0; c < 8; ++c) {
        if (c + 1 < 8) stage_chunk(sm + ((c + 1) & 1) * BUF_SZ, tid, b, pbase, qbase, c + 1);
        const unsigned base = smb + (c & 1) * BUF_SZ;

        #pragma unroll
        for (int k4 = 0; k4 < 4; ++k4) {
            unsigned Ah[2][4], Al[2][4], Bh[4][4], Bl[4][4];
            #pragma unroll
            for (int mf = 0; mf < 2; ++mf) {
                const unsigned gsw = ((unsigned)((2*k4 + gA0) ^ (rA[mf] & 7))) << 4;
                ldm_x4(Ah[mf], base + 0*16384 + rA[mf]*128 + gsw);
                ldm_x4(Al[mf], base + 1*16384 + rA[mf]*128 + gsw);
            }
            #pragma unroll
            for (int t = 0; t < 4; ++t) {
                const unsigned gsw = ((unsigned)((2*k4 + gB0) ^ (nB[t] & 7))) << 4;
                ldm_x4(Bh[t], base + 2*16384 + nB[t]*128 + gsw);
                ldm_x4(Bl[t], base + 3*16384 + nB[t]*128 + gsw);
            }
            #pragma unroll
            for (int mf = 0; mf < 2; ++mf)
                #pragma unroll
                for (int nf = 0; nf < 8; ++nf) {
                    const unsigned* bh = &Bh[nf >> 1][(nf & 1) * 2];
                    const unsigned* bl = &Bl[nf >> 1][(nf & 1) * 2];
                    mma16816(acc[mf][nf], Ah[mf], bh);
                    mma16816(acc[mf][nf], Ah[mf], bl);
                    mma16816(acc[mf][nf], Al[mf], bh);
                }
        }
        __syncthreads();
    }

    // ---- epilogue: dist into sD (stride 129) ----
    float* sD = (float*)sm;
    #pragma unroll
    for (int mf = 0; mf < 2; ++mf) {
        const int lr0 = Rw + 16 * mf + (l >> 2);
        #pragma unroll
        for (int half = 0; half < 2; ++half) {
            const int lr = lr0 + 8 * half;
            const int i  = pbase + lr;
            const int ic = min(i, NNV - 1);
            const float sqi = g_sq[b * NPAD + i];
            const int ri = i / RESO, ci = i - ri * RESO;
            #pragma unroll
            for (int nf = 0; nf < 8; ++nf) {
                #pragma unroll
                for (int e = 0; e < 2; ++e) {
                    const int lc = Cw + 8 * nf + 2 * (l & 3) + e;
                    const int j  = qbase + lc;
                    const int jc = min(j, NNV - 1);
                    const float dot = acc[mf][nf][half * 2 + e];
                    float dv = __fadd_rn(__fsub_rn(__fadd_rn(sqi, g_sq[b * NPAD + j]),
                                                   __fmul_rn(2.0f, dot)),
                                         __ldg(rel + (size_t)ic * NNV + jc));
                    const int rj = j / RESO, cj = j - rj * RESO;
                    if (ri - rj >= -1 && ri - rj <= 1 && ci - cj >= -1 && ci - cj <= 1)
                        dv = __fadd_rn(dv, INF_VAL);
                    sD[lr * SD_ST + lc] = dv;
                }
            }
        }
    }
    __syncthreads();

    // ---- partial top-K scans ----
    const int cq = min(MT, NNV - qbase);
    const int cp = min(MT, NNV - pbase);

    ull list[KK];
    #pragma unroll
    for (int z = 0; z < KK; ++z) list[z] = ~0ULL;

    if (tid < MT) {
        const int i = pbase + tid;
        if (i < NNV) {
            const float* rowp = sD + tid * SD_ST;
            #pragma unroll 4
            for (int ccol = 0; ccol < MT; ++ccol)
                if (ccol < cq)
                    kinsert(list, ((ull)fmap(rowp[ccol]) << 32) | (unsigned)(qbase + ccol));
            write_part(b * NNV + i, q, list);
        }
    } else if (p != q) {
        const int lcol = tid - MT;
        if (lcol < cq) {
            #pragma unroll 4
            for (int r = 0; r < MT; ++r)
                if (r < cp)
                    kinsert(list, ((ull)fmap(sD[r * SD_ST + lcol]) << 32) | (unsigned)(pbase + r));
            write_part(b * NNV + qbase + lcol, p, list);
        }
    }
}

// ---------------- Kernel 3: merge 7 partial lists per row -> edges ----------------
__global__ void __launch_bounds__(256)
merge_kernel(float* __restrict__ out) {
    const int row  = blockIdx.x * 8 + (threadIdx.x >> 5);
    const int lane = threadIdx.x & 31;
    const ull* part = g_part + (size_t)row * (NTB * KK);   // 70 keys

    ull a  = part[lane];
    ull c2 = part[lane + 32];
    ull c3 = (lane < NTB * KK - 64) ? part[lane + 64] : ~0ULL;
    if (c2 < a)  { ull t = a;  a  = c2; c2 = t; }
    if (c3 < c2) { ull t = c2; c2 = c3; c3 = t; }
    if (c2 < a)  { ull t = a;  a  = c2; c2 = t; }

    const int bofs = (row / NNV) * NNV;
    const int base = row * (KK * 3);
    #pragma unroll
    for (int k = 0; k < KK; ++k) {
        ull v = a;
        #pragma unroll
        for (int off = 16; off > 0; off >>= 1) {
            const ull o = __shfl_xor_sync(0xffffffffu, v, off);
            if (o < v) v = o;
        }
        if (lane == k) {
            out[base + 3*k + 0] = (float)((int)(v & 0xffffffffULL) + bofs);  // dst
            out[base + 3*k + 1] = (float)row;                                // src
            out[base + 3*k + 2] = 0.0f;                                      // relation
        }
        if (a == v) { a = c2; c2 = c3; c3 = ~0ULL; }
    }
}

extern "C" void kernel_launch(void* const* d_in, const int* in_sizes, int n_in,
                              void* d_out, int out_size) {
    (void)out_size;
    const float* node_feature = (const float*)d_in[0];
    const float* relative_pos = (const float*)d_in[1];
    if (n_in >= 2 && in_sizes[0] < in_sizes[1]) {
        node_feature = (const float*)d_in[1];
        relative_pos = (const float*)d_in[0];
    }
    float* out = (float*)d_out;

    static int attr_done = 0;
    if (!attr_done) {
        cudaFuncSetAttribute(MediumRangeEdge_11072425689094_kernel,
                             cudaFuncAttributeMaxDynamicSharedMemorySize, SMEM_TOTAL);
        attr_done = 1;
    }

    norm_kernel<<<(BATCH * NNV) / 8, 256>>>(node_feature);
    MediumRangeEdge_11072425689094_kernel<<<BATCH * NPAIR, NTHR, SMEM_TOTAL>>>(relative_pos);
    merge_kernel<<<(BATCH * NNV) / 8, 256>>>(out);
}

// round 16
// speedup vs baseline: 1.5644x; 1.1925x over previous
#include <cuda_runtime.h>
#include <cstdint>

#define BATCH 32
#define NNV   784
#define NPAD  896
#define DD    512
#define RESO  28
#define KK    10
#define MT    128
#define NTB   7
#define NPAIR 28
#define NTHR  256
#define INF_VAL 100000.0f
#define SD_ST 129
#define SUB_SZ   10240          // 128 rows x 80 B
#define STAGE_SZ 40960          // 4 sub-tiles
#define SMEM_TOTAL 81920        // 2 stages

typedef unsigned long long ull;

__device__ __align__(256) unsigned short g_hi[(size_t)BATCH * NPAD * DD];  // zero-padded
__device__ __align__(256) unsigned short g_lo[(size_t)BATCH * NPAD * DD];
__device__ __align__(256) float g_sq[BATCH * NPAD];
__device__ __align__(256) ull   g_part[(size_t)BATCH * NNV * NTB * KK];

// ---------------- helpers ----------------
__device__ __forceinline__ unsigned smem_u32(const void* p) {
    unsigned a;
    asm("{ .reg .u64 t; cvta.to.shared.u64 t, %1; cvt.u32.u64 %0, t; }" : "=r"(a) : "l"(p));
    return a;
}
__device__ __forceinline__ unsigned pack2bf(float lo, float hi) {
    unsigned r;   // first PTX src -> upper half
    asm("cvt.rn.bf16x2.f32 %0, %2, %1;" : "=r"(r) : "f"(lo), "f"(hi));
    return r;
}
__device__ __forceinline__ unsigned fmap(float v) {
    unsigned u = __float_as_uint(v);
    return (u & 0x80000000u) ? ~u : (u | 0x80000000u);
}
__device__ __forceinline__ void kinsert(ull* list, ull key) {
    if (key < list[KK - 1]) {
        list[KK - 1] = key;
        #pragma unroll
        for (int z = KK - 1; z > 0; --z)
            if (list[z] < list[z - 1]) { ull t = list[z-1]; list[z-1] = list[z]; list[z] = t; }
    }
}
__device__ __forceinline__ void write_part(int row, int tile, const ull* list) {
    ull* dst = g_part + ((size_t)row * NTB + tile) * KK;
    #pragma unroll
    for (int m = 0; m < KK; m += 2)
        *(ulonglong2*)(dst + m) = make_ulonglong2(list[m], list[m + 1]);
}
__device__ __forceinline__ void ldm_x4(unsigned* f, unsigned addr) {
    asm volatile("ldmatrix.sync.aligned.m8n8.x4.shared.b16 {%0,%1,%2,%3}, [%4];"
                 : "=r"(f[0]), "=r"(f[1]), "=r"(f[2]), "=r"(f[3]) : "r"(addr));
}
__device__ __forceinline__ void mma16816(float* c, const unsigned* a, const unsigned* b) {
    asm volatile("mma.sync.aligned.m16n8k16.row.col.f32.bf16.bf16.f32 "
                 "{%0,%1,%2,%3}, {%4,%5,%6,%7}, {%8,%9}, {%0,%1,%2,%3};"
                 : "+f"(c[0]), "+f"(c[1]), "+f"(c[2]), "+f"(c[3])
                 : "r"(a[0]), "r"(a[1]), "r"(a[2]), "r"(a[3]), "r"(b[0]), "r"(b[1]));
}
#define CP_ASYNC16(dst, src) \
    asm volatile("cp.async.cg.shared.global [%0], [%1], 16;" :: "r"(dst), "l"(src))
#define CP_COMMIT() asm volatile("cp.async.commit_group;" ::: "memory")
#define CP_WAIT(N)  asm volatile("cp.async.wait_group %0;" :: "n"(N) : "memory")

// ---------------- Kernel 1: normalize + bf16 hi/lo split ----------------
__global__ void norm_kernel(const float* __restrict__ in) {
    const int vec  = blockIdx.x * 8 + (threadIdx.x >> 5);
    const int lane = threadIdx.x & 31;
    const float4* v = reinterpret_cast<const float4*>(in + (size_t)vec * DD);
    float4 a0 = v[lane], a1 = v[lane + 32], a2 = v[lane + 64], a3 = v[lane + 96];

    float s = 0.0f;
    s = fmaf(a0.x,a0.x,s); s = fmaf(a0.y,a0.y,s); s = fmaf(a0.z,a0.z,s); s = fmaf(a0.w,a0.w,s);
    s = fmaf(a1.x,a1.x,s); s = fmaf(a1.y,a1.y,s); s = fmaf(a1.z,a1.z,s); s = fmaf(a1.w,a1.w,s);
    s = fmaf(a2.x,a2.x,s); s = fmaf(a2.y,a2.y,s); s = fmaf(a2.z,a2.z,s); s = fmaf(a2.w,a2.w,s);
    s = fmaf(a3.x,a3.x,s); s = fmaf(a3.y,a3.y,s); s = fmaf(a3.z,a3.z,s); s = fmaf(a3.w,a3.w,s);
    #pragma unroll
    for (int off = 16; off > 0; off >>= 1)
        s = __fadd_rn(s, __shfl_xor_sync(0xffffffffu, s, off));

    const float nrm = fmaxf(__fsqrt_rn(s), 1e-12f);
    a0.x=__fdiv_rn(a0.x,nrm); a0.y=__fdiv_rn(a0.y,nrm); a0.z=__fdiv_rn(a0.z,nrm); a0.w=__fdiv_rn(a0.w,nrm);
    a1.x=__fdiv_rn(a1.x,nrm); a1.y=__fdiv_rn(a1.y,nrm); a1.z=__fdiv_rn(a1.z,nrm); a1.w=__fdiv_rn(a1.w,nrm);
    a2.x=__fdiv_rn(a2.x,nrm); a2.y=__fdiv_rn(a2.y,nrm); a2.z=__fdiv_rn(a2.z,nrm); a2.w=__fdiv_rn(a2.w,nrm);
    a3.x=__fdiv_rn(a3.x,nrm); a3.y=__fdiv_rn(a3.y,nrm); a3.z=__fdiv_rn(a3.z,nrm); a3.w=__fdiv_rn(a3.w,nrm);

    float s2 = 0.0f;
    s2 = fmaf(a0.x,a0.x,s2); s2 = fmaf(a0.y,a0.y,s2); s2 = fmaf(a0.z,a0.z,s2); s2 = fmaf(a0.w,a0.w,s2);
    s2 = fmaf(a1.x,a1.x,s2); s2 = fmaf(a1.y,a1.y,s2); s2 = fmaf(a1.z,a1.z,s2); s2 = fmaf(a1.w,a1.w,s2);
    s2 = fmaf(a2.x,a2.x,s2); s2 = fmaf(a2.y,a2.y,s2); s2 = fmaf(a2.z,a2.z,s2); s2 = fmaf(a2.w,a2.w,s2);
    s2 = fmaf(a3.x,a3.x,s2); s2 = fmaf(a3.y,a3.y,s2); s2 = fmaf(a3.z,a3.z,s2); s2 = fmaf(a3.w,a3.w,s2);
    #pragma unroll
    for (int off = 16; off > 0; off >>= 1)
        s2 = __fadd_rn(s2, __shfl_xor_sync(0xffffffffu, s2, off));

    const int bb = vec / NNV;
    const int ii = vec - bb * NNV;
    ull* H = (ull*)g_hi + (size_t)(bb * NPAD + ii) * (DD / 4);
    ull* L = (ull*)g_lo + (size_t)(bb * NPAD + ii) * (DD / 4);

    const float4 av[4] = {a0, a1, a2, a3};
    #pragma unroll
    for (int t = 0; t < 4; ++t) {
        const float4 a = av[t];
        const unsigned h0 = pack2bf(a.x, a.y);
        const unsigned h1 = pack2bf(a.z, a.w);
        const float lx = a.x - __uint_as_float(h0 << 16);
        const float ly = a.y - __uint_as_float(h0 & 0xFFFF0000u);
        const float lz = a.z - __uint_as_float(h1 << 16);
        const float lw = a.w - __uint_as_float(h1 & 0xFFFF0000u);
        const unsigned l0 = pack2bf(lx, ly);
        const unsigned l1 = pack2bf(lz, lw);
        H[lane + 32 * t] = (ull)h0 | ((ull)h1 << 32);
        L[lane + 32 * t] = (ull)l0 | ((ull)l1 << 32);
    }
    if (lane == 0) g_sq[bb * NPAD + ii] = s2;
}

// ---------------- staging via cp.async: 4 sub-tiles, stride-80 rows ----------------
__device__ __forceinline__ void stage_async(unsigned dstbase, int tid, int b,
                                            int pbase, int qbase, int chunk) {
    #pragma unroll
    for (int st = 0; st < 4; ++st) {
        const unsigned short* src = (st & 1) ? g_lo : g_hi;
        const int rowb = b * NPAD + ((st < 2) ? pbase : qbase);
        const unsigned dsub = dstbase + st * SUB_SZ;
        #pragma unroll
        for (int u = 0; u < 2; ++u) {
            const int idx = tid + 256 * u;
            const int r = idx >> 2, g = idx & 3;
            const unsigned short* s = src + (size_t)(rowb + r) * DD + chunk * 32 + g * 8;
            CP_ASYNC16(dsub + (unsigned)(r * 80 + g * 16), s);
        }
    }
}

// ---------------- Kernel 2: bf16 mma.sync GEMM + dist + partial top-K ----------------
__global__ void __launch_bounds__(NTHR, 2)
MediumRangeEdge_11072425689094_kernel(const float* __restrict__ rel) {
    extern __shared__ char sm[];
    const unsigned smb = smem_u32(sm);

    const int b = blockIdx.x / NPAIR;
    int rem = blockIdx.x - b * NPAIR;
    int p = 0, cnt = NTB;
    while (rem >= cnt) { rem -= cnt; --cnt; ++p; }
    const int q = p + rem;
    const int pbase = p * MT, qbase = q * MT;

    const int tid = threadIdx.x;
    const int w   = tid >> 5;
    const int l   = tid & 31;
    const int Rw  = 32 * (w & 3);          // warp rows
    const int Cw  = 64 * (w >> 2);         // warp cols

    float acc[2][8][4] = {};

    // per-thread ldmatrix geometry (same mapping as the passing R15 kernel)
    int rA[2];  rA[0] = Rw + (l & 15);  rA[1] = rA[0] + 16;
    const int gA0 = (l >> 4) & 1;
    int nB[4];
    #pragma unroll
    for (int t = 0; t < 4; ++t) nB[t] = Cw + 16 * t + (l & 7) + 8 * ((l >> 4) & 1);
    const int gB0 = (l >> 3) & 1;

    stage_async(smb, tid, b, pbase, qbase, 0);
    CP_COMMIT();

    for (int c = 0; c < 16; ++c) {
        if (c + 1 < 16) {
            stage_async(smb + ((c + 1) & 1) * STAGE_SZ, tid, b, pbase, qbase, c + 1);
            CP_COMMIT();
            CP_WAIT(1);
        } else {
            CP_WAIT(0);
        }
        __syncthreads();

        const unsigned base = smb + (c & 1) * STAGE_SZ;
        #pragma unroll
        for (int k4 = 0; k4 < 2; ++k4) {
            const unsigned gk = (unsigned)(2 * k4) * 16u;
            unsigned Ah[2][4], Al[2][4];
            #pragma unroll
            for (int mf = 0; mf < 2; ++mf) {
                const unsigned ra = (unsigned)rA[mf] * 80u + gk + (unsigned)gA0 * 16u;
                ldm_x4(Ah[mf], base + 0 * SUB_SZ + ra);
                ldm_x4(Al[mf], base + 1 * SUB_SZ + ra);
            }
            #pragma unroll
            for (int t = 0; t < 4; ++t) {
                unsigned Bh[4], Bl[4];
                const unsigned rb = (unsigned)nB[t] * 80u + gk + (unsigned)gB0 * 16u;
                ldm_x4(Bh, base + 2 * SUB_SZ + rb);
                ldm_x4(Bl, base + 3 * SUB_SZ + rb);
                #pragma unroll
                for (int mf = 0; mf < 2; ++mf) {
                    #pragma unroll
                    for (int h = 0; h < 2; ++h) {
                        float* a = acc[mf][2 * t + h];
                        mma16816(a, Ah[mf], &Bh[h * 2]);
                        mma16816(a, Ah[mf], &Bl[h * 2]);
                        mma16816(a, Al[mf], &Bh[h * 2]);
                    }
                }
            }
        }
        __syncthreads();
    }

    // ---- epilogue: dist into sD (stride 129) ----
    float* sD = (float*)sm;
    #pragma unroll
    for (int mf = 0; mf < 2; ++mf) {
        const int lr0 = Rw + 16 * mf + (l >> 2);
        #pragma unroll
        for (int half = 0; half < 2; ++half) {
            const int lr = lr0 + 8 * half;
            const int i  = pbase + lr;
            const int ic = min(i, NNV - 1);
            const float sqi = g_sq[b * NPAD + i];
            const int ri = i / RESO, ci = i - ri * RESO;
            #pragma unroll
            for (int nf = 0; nf < 8; ++nf) {
                #pragma unroll
                for (int e = 0; e < 2; ++e) {
                    const int lc = Cw + 8 * nf + 2 * (l & 3) + e;
                    const int j  = qbase + lc;
                    const int jc = min(j, NNV - 1);
                    const float dot = acc[mf][nf][half * 2 + e];
                    float dv = __fadd_rn(__fsub_rn(__fadd_rn(sqi, g_sq[b * NPAD + j]),
                                                   __fmul_rn(2.0f, dot)),
                                         __ldg(rel + (size_t)ic * NNV + jc));
                    const int rj = j / RESO, cj = j - rj * RESO;
                    if (ri - rj >= -1 && ri - rj <= 1 && ci - cj >= -1 && ci - cj <= 1)
                        dv = __fadd_rn(dv, INF_VAL);
                    sD[lr * SD_ST + lc] = dv;
                }
            }
        }
    }
    __syncthreads();

    // ---- partial top-K scans ----
    const int cq = min(MT, NNV - qbase);
    const int cp = min(MT, NNV - pbase);

    ull list[KK];
    #pragma unroll
    for (int z = 0; z < KK; ++z) list[z] = ~0ULL;

    if (tid < MT) {
        const int i = pbase + tid;
        if (i < NNV) {
            const float* rowp = sD + tid * SD_ST;
            #pragma unroll 4
            for (int ccol = 0; ccol < MT; ++ccol)
                if (ccol < cq)
                    kinsert(list, ((ull)fmap(rowp[ccol]) << 32) | (unsigned)(qbase + ccol));
            write_part(b * NNV + i, q, list);
        }
    } else if (p != q) {
        const int lcol = tid - MT;
        if (lcol < cq) {
            #pragma unroll 4
            for (int r = 0; r < MT; ++r)
                if (r < cp)
                    kinsert(list, ((ull)fmap(sD[r * SD_ST + lcol]) << 32) | (unsigned)(pbase + r));
            write_part(b * NNV + qbase + lcol, p, list);
        }
    }
}

// ---------------- Kernel 3: merge 7 partial lists per row -> edges ----------------
__global__ void __launch_bounds__(256)
merge_kernel(float* __restrict__ out) {
    const int row  = blockIdx.x * 8 + (threadIdx.x >> 5);
    const int lane = threadIdx.x & 31;
    const ull* part = g_part + (size_t)row * (NTB * KK);   // 70 keys

    ull a  = part[lane];
    ull c2 = part[lane + 32];
    ull c3 = (lane < NTB * KK - 64) ? part[lane + 64] : ~0ULL;
    if (c2 < a)  { ull t = a;  a  = c2; c2 = t; }
    if (c3 < c2) { ull t = c2; c2 = c3; c3 = t; }
    if (c2 < a)  { ull t = a;  a  = c2; c2 = t; }

    const int bofs = (row / NNV) * NNV;
    const int base = row * (KK * 3);
    #pragma unroll
    for (int k = 0; k < KK; ++k) {
        ull v = a;
        #pragma unroll
        for (int off = 16; off > 0; off >>= 1) {
            const ull o = __shfl_xor_sync(0xffffffffu, v, off);
            if (o < v) v = o;
        }
        if (lane == k) {
            out[base + 3*k + 0] = (float)((int)(v & 0xffffffffULL) + bofs);  // dst
            out[base + 3*k + 1] = (float)row;                                // src
            out[base + 3*k + 2] = 0.0f;                                      // relation
        }
        if (a == v) { a = c2; c2 = c3; c3 = ~0ULL; }
    }
}

extern "C" void kernel_launch(void* const* d_in, const int* in_sizes, int n_in,
                              void* d_out, int out_size) {
    (void)out_size;
    const float* node_feature = (const float*)d_in[0];
    const float* relative_pos = (const float*)d_in[1];
    if (n_in >= 2 && in_sizes[0] < in_sizes[1]) {
        node_feature = (const float*)d_in[1];
        relative_pos = (const float*)d_in[0];
    }
    float* out = (float*)d_out;

    static int attr_done = 0;
    if (!attr_done) {
        cudaFuncSetAttribute(MediumRangeEdge_11072425689094_kernel,
                             cudaFuncAttributeMaxDynamicSharedMemorySize, SMEM_TOTAL);
        attr_done = 1;
    }

    norm_kernel<<<(BATCH * NNV) / 8, 256>>>(node_feature);
    MediumRangeEdge_11072425689094_kernel<<<BATCH * NPAIR, NTHR, SMEM_TOTAL>>>(relative_pos);
    merge_kernel<<<(BATCH * NNV) / 8, 256>>>(out);
}

// round 17
// speedup vs baseline: 1.6212x; 1.0364x over previous
#include <cuda_runtime.h>
#include <cstdint>

#define BATCH 32
#define NNV   784
#define NPAD  896
#define DD    512
#define RESO  28
#define KK    10
#define MT    128
#define NTB   7
#define NPAIR 28
#define NTHR  256
#define INF_VAL 100000.0f
#define SD_ST 129
#define SUB_SZ   10240          // 128 rows x 80 B
#define STAGE_SZ 40960          // 4 sub-tiles
#define SMEM_TOTAL 81920        // 2 stages

typedef unsigned long long ull;

__device__ __align__(256) unsigned short g_hi[(size_t)BATCH * NPAD * DD];  // zero-padded
__device__ __align__(256) unsigned short g_lo[(size_t)BATCH * NPAD * DD];
__device__ __align__(256) float g_sq[BATCH * NPAD];
__device__ __align__(256) ull   g_part[(size_t)BATCH * NNV * NTB * KK];

// ---------------- helpers ----------------
__device__ __forceinline__ unsigned smem_u32(const void* p) {
    unsigned a;
    asm("{ .reg .u64 t; cvta.to.shared.u64 t, %1; cvt.u32.u64 %0, t; }" : "=r"(a) : "l"(p));
    return a;
}
__device__ __forceinline__ unsigned pack2bf(float lo, float hi) {
    unsigned r;   // first PTX src -> upper half
    asm("cvt.rn.bf16x2.f32 %0, %2, %1;" : "=r"(r) : "f"(lo), "f"(hi));
    return r;
}
__device__ __forceinline__ unsigned fmap(float v) {
    unsigned u = __float_as_uint(v);
    return (u & 0x80000000u) ? ~u : (u | 0x80000000u);
}
__device__ __forceinline__ void kinsert(ull* list, ull key) {
    if (key < list[KK - 1]) {
        list[KK - 1] = key;
        #pragma unroll
        for (int z = KK - 1; z > 0; --z)
            if (list[z] < list[z - 1]) { ull t = list[z-1]; list[z-1] = list[z]; list[z] = t; }
    }
}
__device__ __forceinline__ void write_part(int row, int tile, const ull* list) {
    ull* dst = g_part + ((size_t)row * NTB + tile) * KK;
    #pragma unroll
    for (int m = 0; m < KK; m += 2)
        *(ulonglong2*)(dst + m) = make_ulonglong2(list[m], list[m + 1]);
}
__device__ __forceinline__ void ldm_x4(unsigned* f, unsigned addr) {
    asm volatile("ldmatrix.sync.aligned.m8n8.x4.shared.b16 {%0,%1,%2,%3}, [%4];"
                 : "=r"(f[0]), "=r"(f[1]), "=r"(f[2]), "=r"(f[3]) : "r"(addr));
}
__device__ __forceinline__ void mma16816(float* c, const unsigned* a, const unsigned* b) {
    asm volatile("mma.sync.aligned.m16n8k16.row.col.f32.bf16.bf16.f32 "
                 "{%0,%1,%2,%3}, {%4,%5,%6,%7}, {%8,%9}, {%0,%1,%2,%3};"
                 : "+f"(c[0]), "+f"(c[1]), "+f"(c[2]), "+f"(c[3])
                 : "r"(a[0]), "r"(a[1]), "r"(a[2]), "r"(a[3]), "r"(b[0]), "r"(b[1]));
}
#define CP_ASYNC16(dst, src) \
    asm volatile("cp.async.cg.shared.global [%0], [%1], 16;" :: "r"(dst), "l"(src))
#define CP_COMMIT() asm volatile("cp.async.commit_group;" ::: "memory")
#define CP_WAIT(N)  asm volatile("cp.async.wait_group %0;" :: "n"(N) : "memory")

// ---------------- Kernel 1: normalize + bf16 hi/lo split ----------------
__global__ void norm_kernel(const float* __restrict__ in) {
    const int vec  = blockIdx.x * 8 + (threadIdx.x >> 5);
    const int lane = threadIdx.x & 31;
    const float4* v = reinterpret_cast<const float4*>(in + (size_t)vec * DD);
    float4 a0 = v[lane], a1 = v[lane + 32], a2 = v[lane + 64], a3 = v[lane + 96];

    float s = 0.0f;
    s = fmaf(a0.x,a0.x,s); s = fmaf(a0.y,a0.y,s); s = fmaf(a0.z,a0.z,s); s = fmaf(a0.w,a0.w,s);
    s = fmaf(a1.x,a1.x,s); s = fmaf(a1.y,a1.y,s); s = fmaf(a1.z,a1.z,s); s = fmaf(a1.w,a1.w,s);
    s = fmaf(a2.x,a2.x,s); s = fmaf(a2.y,a2.y,s); s = fmaf(a2.z,a2.z,s); s = fmaf(a2.w,a2.w,s);
    s = fmaf(a3.x,a3.x,s); s = fmaf(a3.y,a3.y,s); s = fmaf(a3.z,a3.z,s); s = fmaf(a3.w,a3.w,s);
    #pragma unroll
    for (int off = 16; off > 0; off >>= 1)
        s = __fadd_rn(s, __shfl_xor_sync(0xffffffffu, s, off));

    const float nrm = fmaxf(__fsqrt_rn(s), 1e-12f);
    a0.x=__fdiv_rn(a0.x,nrm); a0.y=__fdiv_rn(a0.y,nrm); a0.z=__fdiv_rn(a0.z,nrm); a0.w=__fdiv_rn(a0.w,nrm);
    a1.x=__fdiv_rn(a1.x,nrm); a1.y=__fdiv_rn(a1.y,nrm); a1.z=__fdiv_rn(a1.z,nrm); a1.w=__fdiv_rn(a1.w,nrm);
    a2.x=__fdiv_rn(a2.x,nrm); a2.y=__fdiv_rn(a2.y,nrm); a2.z=__fdiv_rn(a2.z,nrm); a2.w=__fdiv_rn(a2.w,nrm);
    a3.x=__fdiv_rn(a3.x,nrm); a3.y=__fdiv_rn(a3.y,nrm); a3.z=__fdiv_rn(a3.z,nrm); a3.w=__fdiv_rn(a3.w,nrm);

    float s2 = 0.0f;
    s2 = fmaf(a0.x,a0.x,s2); s2 = fmaf(a0.y,a0.y,s2); s2 = fmaf(a0.z,a0.z,s2); s2 = fmaf(a0.w,a0.w,s2);
    s2 = fmaf(a1.x,a1.x,s2); s2 = fmaf(a1.y,a1.y,s2); s2 = fmaf(a1.z,a1.z,s2); s2 = fmaf(a1.w,a1.w,s2);
    s2 = fmaf(a2.x,a2.x,s2); s2 = fmaf(a2.y,a2.y,s2); s2 = fmaf(a2.z,a2.z,s2); s2 = fmaf(a2.w,a2.w,s2);
    s2 = fmaf(a3.x,a3.x,s2); s2 = fmaf(a3.y,a3.y,s2); s2 = fmaf(a3.z,a3.z,s2); s2 = fmaf(a3.w,a3.w,s2);
    #pragma unroll
    for (int off = 16; off > 0; off >>= 1)
        s2 = __fadd_rn(s2, __shfl_xor_sync(0xffffffffu, s2, off));

    const int bb = vec / NNV;
    const int ii = vec - bb * NNV;
    ull* H = (ull*)g_hi + (size_t)(bb * NPAD + ii) * (DD / 4);
    ull* L = (ull*)g_lo + (size_t)(bb * NPAD + ii) * (DD / 4);

    const float4 av[4] = {a0, a1, a2, a3};
    #pragma unroll
    for (int t = 0; t < 4; ++t) {
        const float4 a = av[t];
        const unsigned h0 = pack2bf(a.x, a.y);
        const unsigned h1 = pack2bf(a.z, a.w);
        const float lx = a.x - __uint_as_float(h0 << 16);
        const float ly = a.y - __uint_as_float(h0 & 0xFFFF0000u);
        const float lz = a.z - __uint_as_float(h1 << 16);
        const float lw = a.w - __uint_as_float(h1 & 0xFFFF0000u);
        const unsigned l0 = pack2bf(lx, ly);
        const unsigned l1 = pack2bf(lz, lw);
        H[lane + 32 * t] = (ull)h0 | ((ull)h1 << 32);
        L[lane + 32 * t] = (ull)l0 | ((ull)l1 << 32);
    }
    if (lane == 0) g_sq[bb * NPAD + ii] = s2;
}

// ---------------- staging via cp.async (row-predicated) ----------------
__device__ __forceinline__ void stage_async(unsigned dstbase, int tid, int b,
                                            int pbase, int qbase, int chunk,
                                            int prows, int qrows) {
    #pragma unroll
    for (int st = 0; st < 4; ++st) {
        const unsigned short* src = (st & 1) ? g_lo : g_hi;
        const int rowb = b * NPAD + ((st < 2) ? pbase : qbase);
        const int lim  = (st < 2) ? prows : qrows;
        const unsigned dsub = dstbase + st * SUB_SZ;
        #pragma unroll
        for (int u = 0; u < 2; ++u) {
            const int idx = tid + 256 * u;
            const int r = idx >> 2, g = idx & 3;
            if (r < lim) {
                const unsigned short* s = src + (size_t)(rowb + r) * DD + chunk * 32 + g * 8;
                CP_ASYNC16(dsub + (unsigned)(r * 80 + g * 16), s);
            }
        }
    }
}

// ---------------- mma for one staged 32-k chunk (TMAX = active B n16-groups) ----------------
template<int TMAX>
__device__ __forceinline__ void mma_chunk(unsigned base, const int* rA, int gA0,
                                          const int* nB, int gB0, float acc[2][8][4]) {
    #pragma unroll
    for (int k4 = 0; k4 < 2; ++k4) {
        const unsigned gk = (unsigned)(2 * k4) * 16u;
        unsigned Ah[2][4], Al[2][4];
        #pragma unroll
        for (int mf = 0; mf < 2; ++mf) {
            const unsigned ra = (unsigned)rA[mf] * 80u + gk + (unsigned)gA0 * 16u;
            ldm_x4(Ah[mf], base + 0 * SUB_SZ + ra);
            ldm_x4(Al[mf], base + 1 * SUB_SZ + ra);
        }
        #pragma unroll
        for (int t = 0; t < TMAX; ++t) {
            unsigned Bh[4], Bl[4];
            const unsigned rb = (unsigned)nB[t] * 80u + gk + (unsigned)gB0 * 16u;
            ldm_x4(Bh, base + 2 * SUB_SZ + rb);
            ldm_x4(Bl, base + 3 * SUB_SZ + rb);
            #pragma unroll
            for (int mf = 0; mf < 2; ++mf) {
                #pragma unroll
                for (int h = 0; h < 2; ++h) {
                    float* a = acc[mf][2 * t + h];
                    mma16816(a, Ah[mf], &Bh[h * 2]);
                    mma16816(a, Ah[mf], &Bl[h * 2]);
                    mma16816(a, Al[mf], &Bh[h * 2]);
                }
            }
        }
    }
}

// ---------------- Kernel 2: bf16 mma.sync GEMM + dist + partial top-K ----------------
__global__ void __launch_bounds__(NTHR, 2)
MediumRangeEdge_11072425689094_kernel(const float* __restrict__ rel) {
    extern __shared__ char sm[];
    const unsigned smb = smem_u32(sm);

    const int b = blockIdx.x / NPAIR;
    int rem = blockIdx.x - b * NPAIR;
    int p = 0, cnt = NTB;
    while (rem >= cnt) { rem -= cnt; --cnt; ++p; }
    const int q = p + rem;
    const int pbase = p * MT, qbase = q * MT;

    const int cq = min(MT, NNV - qbase);
    const int cp = min(MT, NNV - pbase);
    const bool qlast = (cq < MT);          // tile 6: only 16 valid cols
    const bool diag  = (p == q);

    const int tid = threadIdx.x;
    const int w   = tid >> 5;
    const int l   = tid & 31;
    const int Rw  = 32 * (w & 3);          // warp rows
    const int Cw  = 64 * (w >> 2);         // warp cols

    // warps with nothing useful to compute skip mma entirely
    const bool warp_active = !(qlast && Cw == 64) && !(diag && Rw >= Cw + 64);

    float acc[2][8][4] = {};

    int rA[2];  rA[0] = Rw + (l & 15);  rA[1] = rA[0] + 16;
    const int gA0 = (l >> 4) & 1;
    int nB[4];
    #pragma unroll
    for (int t = 0; t < 4; ++t) nB[t] = Cw + 16 * t + (l & 7) + 8 * ((l >> 4) & 1);
    const int gB0 = (l >> 3) & 1;

    stage_async(smb, tid, b, pbase, qbase, 0, cp, cq);
    CP_COMMIT();

    for (int c = 0; c < 16; ++c) {
        if (c + 1 < 16) {
            stage_async(smb + ((c + 1) & 1) * STAGE_SZ, tid, b, pbase, qbase, c + 1, cp, cq);
            CP_COMMIT();
            CP_WAIT(1);
        } else {
            CP_WAIT(0);
        }
        __syncthreads();

        const unsigned base = smb + (c & 1) * STAGE_SZ;
        if (warp_active) {
            if (qlast) mma_chunk<1>(base, rA, gA0, nB, gB0, acc);
            else       mma_chunk<4>(base, rA, gA0, nB, gB0, acc);
        }
        __syncthreads();
    }

    // ---- epilogue: dist into sD (stride 129) ----
    float* sD = (float*)sm;
    #pragma unroll
    for (int mf = 0; mf < 2; ++mf) {
        const int lr0 = Rw + 16 * mf + (l >> 2);
        #pragma unroll
        for (int half = 0; half < 2; ++half) {
            const int lr = lr0 + 8 * half;
            const int i  = pbase + lr;
            const int ic = min(i, NNV - 1);
            const float sqi = g_sq[b * NPAD + i];
            const int ri = i / RESO, ci = i - ri * RESO;
            #pragma unroll
            for (int nf = 0; nf < 8; ++nf) {
                #pragma unroll
                for (int e = 0; e < 2; ++e) {
                    const int lc = Cw + 8 * nf + 2 * (l & 3) + e;
                    const int j  = qbase + lc;
                    const int jc = min(j, NNV - 1);
                    const float dot = acc[mf][nf][half * 2 + e];
                    float dv = __fadd_rn(__fsub_rn(__fadd_rn(sqi, g_sq[b * NPAD + j]),
                                                   __fmul_rn(2.0f, dot)),
                                         __ldg(rel + (size_t)ic * NNV + jc));
                    const int rj = j / RESO, cj = j - rj * RESO;
                    if (ri - rj >= -1 && ri - rj <= 1 && ci - cj >= -1 && ci - cj <= 1)
                        dv = __fadd_rn(dv, INF_VAL);
                    sD[lr * SD_ST + lc] = dv;
                }
            }
        }
    }
    __syncthreads();

    // diagonal blocks: fill the skipped lower-left region by mirroring
    if (diag) {
        for (int m = tid; m < 64 * 64; m += NTHR) {
            const int r = 64 + (m >> 6), cc2 = m & 63;
            sD[r * SD_ST + cc2] = sD[cc2 * SD_ST + r];
        }
        __syncthreads();
    }

    // ---- partial top-K scans ----
    ull list[KK];
    #pragma unroll
    for (int z = 0; z < KK; ++z) list[z] = ~0ULL;

    if (tid < MT) {
        const int i = pbase + tid;
        if (i < NNV) {
            const float* rowp = sD + tid * SD_ST;
            #pragma unroll 4
            for (int ccol = 0; ccol < MT; ++ccol)
                if (ccol < cq)
                    kinsert(list, ((ull)fmap(rowp[ccol]) << 32) | (unsigned)(qbase + ccol));
            write_part(b * NNV + i, q, list);
        }
    } else if (p != q) {
        const int lcol = tid - MT;
        if (lcol < cq) {
            #pragma unroll 4
            for (int r = 0; r < MT; ++r)
                if (r < cp)
                    kinsert(list, ((ull)fmap(sD[r * SD_ST + lcol]) << 32) | (unsigned)(pbase + r));
            write_part(b * NNV + qbase + lcol, p, list);
        }
    }
}

// ---------------- Kernel 3: merge 7 partial lists per row -> edges ----------------
__global__ void __launch_bounds__(256)
merge_kernel(float* __restrict__ out) {
    const int row  = blockIdx.x * 8 + (threadIdx.x >> 5);
    const int lane = threadIdx.x & 31;
    const ull* part = g_part + (size_t)row * (NTB * KK);   // 70 keys

    ull a  = part[lane];
    ull c2 = part[lane + 32];
    ull c3 = (lane < NTB * KK - 64) ? part[lane + 64] : ~0ULL;
    if (c2 < a)  { ull t = a;  a  = c2; c2 = t; }
    if (c3 < c2) { ull t = c2; c2 = c3; c3 = t; }
    if (c2 < a)  { ull t = a;  a  = c2; c2 = t; }

    const int bofs = (row / NNV) * NNV;
    const int base = row * (KK * 3);
    #pragma unroll
    for (int k = 0; k < KK; ++k) {
        ull v = a;
        #pragma unroll
        for (int off = 16; off > 0; off >>= 1) {
            const ull o = __shfl_xor_sync(0xffffffffu, v, off);
            if (o < v) v = o;
        }
        if (lane == k) {
            out[base + 3*k + 0] = (float)((int)(v & 0xffffffffULL) + bofs);  // dst
            out[base + 3*k + 1] = (float)row;                                // src
            out[base + 3*k + 2] = 0.0f;                                      // relation
        }
        if (a == v) { a = c2; c2 = c3; c3 = ~0ULL; }
    }
}

extern "C" void kernel_launch(void* const* d_in, const int* in_sizes, int n_in,
                              void* d_out, int out_size) {
    (void)out_size;
    const float* node_feature = (const float*)d_in[0];
    const float* relative_pos = (const float*)d_in[1];
    if (n_in >= 2 && in_sizes[0] < in_sizes[1]) {
        node_feature = (const float*)d_in[1];
        relative_pos = (const float*)d_in[0];
    }
    float* out = (float*)d_out;

    static int attr_done = 0;
    if (!attr_done) {
        cudaFuncSetAttribute(MediumRangeEdge_11072425689094_kernel,
                             cudaFuncAttributeMaxDynamicSharedMemorySize, SMEM_TOTAL);
        attr_done = 1;
    }

    norm_kernel<<<(BATCH * NNV) / 8, 256>>>(node_feature);
    MediumRangeEdge_11072425689094_kernel<<<BATCH * NPAIR, NTHR, SMEM_TOTAL>>>(relative_pos);
    merge_kernel<<<(BATCH * NNV) / 8, 256>>>(out);
}